// round 3
// baseline (speedup 1.0000x reference)
#include <cuda_runtime.h>
#include <cuda_fp16.h>
#include <cstdint>
#include <cstddef>

#define NNODE 8192
#define DFEAT 128
#define SEC   1048576  // 8192*128

// ---------------- scratch (allocation-free __device__ globals) ----------------
__device__ __align__(16) __half g_adj16[(size_t)NNODE * NNODE]; // adj*8192 fp16 (128 MB)
__device__ __align__(16) __half g_B16[(size_t)NNODE * DFEAT];   // (h@W) fp16 row-major (2 MB)
__device__ __align__(16) float  g_H[(size_t)NNODE * DFEAT];     // current h fp32 (4 MB)
__device__ __align__(16) float  g_sums[2 * DFEAT];

// ---------------- baseline-PTX helpers (all sm_80-era; safe on .target sm_103) --------
__device__ __forceinline__ uint32_t smem_u32(const void* p) {
    uint32_t a;
    asm("{ .reg .u64 t; cvta.to.shared.u64 t, %1; cvt.u32.u64 %0, t; }" : "=r"(a) : "l"(p));
    return a;
}
__device__ __forceinline__ void cp16(uint32_t saddr, const void* gaddr) {
    asm volatile("cp.async.cg.shared.global [%0], [%1], 16;" :: "r"(saddr), "l"(gaddr));
}
#define CP_COMMIT() asm volatile("cp.async.commit_group;" ::: "memory")
#define CP_WAIT1()  asm volatile("cp.async.wait_group 1;" ::: "memory")

__device__ __forceinline__ void ldsm4(uint32_t& r0, uint32_t& r1, uint32_t& r2, uint32_t& r3,
                                      uint32_t a) {
    asm volatile("ldmatrix.sync.aligned.m8n8.x4.shared.b16 {%0,%1,%2,%3}, [%4];"
                 : "=r"(r0), "=r"(r1), "=r"(r2), "=r"(r3) : "r"(a));
}
__device__ __forceinline__ void ldsm4t(uint32_t& r0, uint32_t& r1, uint32_t& r2, uint32_t& r3,
                                       uint32_t a) {
    asm volatile("ldmatrix.sync.aligned.m8n8.x4.trans.shared.b16 {%0,%1,%2,%3}, [%4];"
                 : "=r"(r0), "=r"(r1), "=r"(r2), "=r"(r3) : "r"(a));
}
__device__ __forceinline__ void mma16816(float* c, const uint32_t* a, uint32_t b0, uint32_t b1) {
    asm volatile(
        "mma.sync.aligned.m16n8k16.row.col.f32.f16.f16.f32 "
        "{%0,%1,%2,%3}, {%4,%5,%6,%7}, {%8,%9}, {%0,%1,%2,%3};"
        : "+f"(c[0]), "+f"(c[1]), "+f"(c[2]), "+f"(c[3])
        : "r"(a[0]), "r"(a[1]), "r"(a[2]), "r"(a[3]), "r"(b0), "r"(b1));
}

#define SWA(o) ((o) ^ (((o) >> 3) & 0x70))   // 128B-row swizzle (A tile)
#define SWB(o) ((o) ^ (((o) >> 4) & 0xF0))   // 256B-row swizzle (B tile)

// ---------------- kernels ----------------

// adj fp32 -> fp16 * 8192
__global__ void __launch_bounds__(256) k_convert(const float* __restrict__ adj) {
    size_t i = ((size_t)blockIdx.x * 256 + threadIdx.x) * 8;
    float4 a = *(const float4*)(adj + i);
    float4 b = *(const float4*)(adj + i + 4);
    __half2 h0 = __floats2half2_rn(a.x * 8192.f, a.y * 8192.f);
    __half2 h1 = __floats2half2_rn(a.z * 8192.f, a.w * 8192.f);
    __half2 h2 = __floats2half2_rn(b.x * 8192.f, b.y * 8192.f);
    __half2 h3 = __floats2half2_rn(b.z * 8192.f, b.w * 8192.f);
    uint4 o;
    o.x = *(uint32_t*)&h0; o.y = *(uint32_t*)&h1;
    o.z = *(uint32_t*)&h2; o.w = *(uint32_t*)&h3;
    *(uint4*)(&g_adj16[i]) = o;
}

// x_m -> out sec0 + g_H ; mask -> out sec3
__global__ void __launch_bounds__(256) k_mask(const float* __restrict__ x,
                                              const float* __restrict__ mask,
                                              const float* __restrict__ noise,
                                              float* __restrict__ out) {
    size_t g = ((size_t)blockIdx.x * 256 + threadIdx.x) * 4;
    float4 xv = *(const float4*)(x + g);
    float4 mv = *(const float4*)(mask + g);
    float4 nv = *(const float4*)(noise + g);
    float4 v;
    v.x = xv.x * (1.f - mv.x) + nv.x * mv.x;
    v.y = xv.y * (1.f - mv.y) + nv.y * mv.y;
    v.z = xv.z * (1.f - mv.z) + nv.z * mv.z;
    v.w = xv.w * (1.f - mv.w) + nv.w * mv.w;
    *(float4*)(out + g) = v;
    *(float4*)(out + 3 * (size_t)SEC + g) = mv;
    *(float4*)(g_H + g) = v;
}

// HW = g_H @ W in exact fp32; quantize to fp16 row-major g_B16. Zeroes g_sums.
// 128 blocks x 64 rows; warp w -> cols w*16..+15, lane l -> rows l and l+32.
__global__ void __launch_bounds__(256) k_hw(const float* __restrict__ W) {
    extern __shared__ float sm_hw[];
    float* Hs = sm_hw;              // [64][129]
    float* Ws = sm_hw + 64 * 129;   // [128][128]
    int tid = threadIdx.x;
    int r0 = blockIdx.x * 64;
    if (blockIdx.x == 0) g_sums[tid] = 0.f;

#pragma unroll
    for (int j = 0; j < 8; j++) {
        int v = tid + j * 256;
        int row = v >> 5, c4 = (v & 31) * 4;
        float4 f = *(const float4*)(g_H + (size_t)(r0 + row) * 128 + c4);
        float* d = Hs + row * 129 + c4;
        d[0] = f.x; d[1] = f.y; d[2] = f.z; d[3] = f.w;
    }
#pragma unroll
    for (int j = 0; j < 16; j++)
        ((float4*)Ws)[tid + j * 256] = ((const float4*)W)[tid + j * 256];
    __syncthreads();

    int l = tid & 31, w = tid >> 5, cw = w * 16;
    float accA[16], accB[16];
#pragma unroll
    for (int j = 0; j < 16; j++) { accA[j] = 0.f; accB[j] = 0.f; }

#pragma unroll 4
    for (int k = 0; k < 128; k++) {
        float a0 = Hs[l * 129 + k];
        float a1 = Hs[(l + 32) * 129 + k];
        const float4* wr = (const float4*)(Ws + k * 128 + cw);
#pragma unroll
        for (int q = 0; q < 4; q++) {
            float4 wv = wr[q];
            accA[q * 4 + 0] += a0 * wv.x; accA[q * 4 + 1] += a0 * wv.y;
            accA[q * 4 + 2] += a0 * wv.z; accA[q * 4 + 3] += a0 * wv.w;
            accB[q * 4 + 0] += a1 * wv.x; accB[q * 4 + 1] += a1 * wv.y;
            accB[q * 4 + 2] += a1 * wv.z; accB[q * 4 + 3] += a1 * wv.w;
        }
    }
    int rA = r0 + l, rB = rA + 32;
#pragma unroll
    for (int j = 0; j < 8; j++) {
        int c0 = cw + 2 * j;
        *(__half2*)&g_B16[(size_t)rA * 128 + c0] = __floats2half2_rn(accA[2 * j], accA[2 * j + 1]);
        *(__half2*)&g_B16[(size_t)rB * 128 + c0] = __floats2half2_rn(accB[2 * j], accB[2 * j + 1]);
    }
}

// Big GEMM: P = adj16 @ B16 ; z = prelu(P/8192 + bias) -> g_H or out.
// 128 CTAs x (M=64, N=128), K-chunks of 64, 3-stage cp.async pipeline, mma.sync HMMA.
__global__ void __launch_bounds__(256) k_big(const float* __restrict__ bias,
                                             const float* __restrict__ alpha,
                                             float* __restrict__ outp, int to_out) {
    extern __shared__ char smem[];
    uint32_t sb = smem_u32(smem);
    const int tid = threadIdx.x, w = tid >> 5, l = tid & 31;
    const int wm = w >> 2, wn = w & 3;     // 2x4 warp grid (m32 x n32 warp tiles)
    const int m0 = blockIdx.x * 64;
    const __half* Ag = g_adj16;
    const __half* Bg = g_B16;

    auto load_stage = [&](int slot, int t) {
        uint32_t as = sb + slot * 24576;
        uint32_t bs = as + 8192;
#pragma unroll
        for (int i = 0; i < 2; i++) {          // A: 64 rows x 128B
            int idx = tid + i * 256;
            int row = idx >> 3, u = idx & 7;
            const void* g = Ag + (size_t)(m0 + row) * NNODE + t * 64 + u * 8;
            uint32_t off = (uint32_t)(row * 128 + u * 16);
            cp16(as + SWA(off), g);
        }
#pragma unroll
        for (int i = 0; i < 4; i++) {          // B: 64 rows x 256B
            int idx = tid + i * 256;
            int row = idx >> 4, u = idx & 15;
            const void* g = Bg + (size_t)(t * 64 + row) * 128 + u * 8;
            uint32_t off = (uint32_t)(row * 256 + u * 16);
            cp16(bs + SWB(off), g);
        }
    };

    float acc[2][4][4];
#pragma unroll
    for (int i = 0; i < 2; i++)
#pragma unroll
        for (int j = 0; j < 4; j++)
#pragma unroll
            for (int q = 0; q < 4; q++) acc[i][j][q] = 0.f;

    load_stage(0, 0); CP_COMMIT();
    load_stage(1, 1); CP_COMMIT();

    for (int t = 0; t < 128; ++t) {
        CP_WAIT1();
        __syncthreads();
        if (t + 2 < 128) load_stage((t + 2) % 3, t + 2);
        CP_COMMIT();

        uint32_t as = sb + (t % 3) * 24576;
        uint32_t bs = as + 8192;
#pragma unroll
        for (int kk = 0; kk < 4; kk++) {
            uint32_t a[2][4], b[2][4];
#pragma unroll
            for (int ti = 0; ti < 2; ti++) {
                int mrow = wm * 32 + ti * 16 + (l & 15);
                int kcol = kk * 16 + (l >> 4) * 8;
                uint32_t off = (uint32_t)(mrow * 128 + kcol * 2);
                ldsm4(a[ti][0], a[ti][1], a[ti][2], a[ti][3], as + SWA(off));
            }
#pragma unroll
            for (int tj2 = 0; tj2 < 2; tj2++) {
                int krow = kk * 16 + (l & 15);
                int ncol = wn * 32 + tj2 * 16 + (l >> 4) * 8;
                uint32_t off = (uint32_t)(krow * 256 + ncol * 2);
                ldsm4t(b[tj2][0], b[tj2][1], b[tj2][2], b[tj2][3], bs + SWB(off));
            }
#pragma unroll
            for (int ti = 0; ti < 2; ti++)
#pragma unroll
                for (int tj = 0; tj < 4; tj++)
                    mma16816(acc[ti][tj], a[ti], b[tj >> 1][2 * (tj & 1)],
                             b[tj >> 1][2 * (tj & 1) + 1]);
        }
        __syncthreads();
    }

    // epilogue: /8192 + bias + prelu
    float al = alpha[0];
    const float s = 1.f / 8192.f;
    float* dst = to_out ? outp : g_H;
#pragma unroll
    for (int ti = 0; ti < 2; ti++) {
        int row = m0 + wm * 32 + ti * 16 + (l >> 2);
#pragma unroll
        for (int tj = 0; tj < 4; tj++) {
            int col = wn * 32 + tj * 8 + (l & 3) * 2;
            float2 bb = *(const float2*)(bias + col);
            float v0 = acc[ti][tj][0] * s + bb.x;
            float v1 = acc[ti][tj][1] * s + bb.y;
            float v2 = acc[ti][tj][2] * s + bb.x;
            float v3 = acc[ti][tj][3] * s + bb.y;
            v0 = v0 >= 0.f ? v0 : al * v0;
            v1 = v1 >= 0.f ? v1 : al * v1;
            v2 = v2 >= 0.f ? v2 : al * v2;
            v3 = v3 >= 0.f ? v3 : al * v3;
            float2 p0 = make_float2(v0, v1), p1 = make_float2(v2, v3);
            *(float2*)(dst + (size_t)row * 128 + col) = p0;
            *(float2*)(dst + (size_t)(row + 8) * 128 + col) = p1;
        }
    }
}

// per-column sums over 128-row slab -> global atomics
__global__ void __launch_bounds__(256) k_colstats() {
    __shared__ float ss[256], sq[256];
    int tid = threadIdx.x;
    int c = tid & 127, half = tid >> 7;
    const float* p = g_H + (size_t)(blockIdx.x * 128 + half * 64) * 128 + c;
    float s = 0.f, q = 0.f;
#pragma unroll 8
    for (int j = 0; j < 64; j++) { float v = p[(size_t)j * 128]; s += v; q += v * v; }
    ss[tid] = s; sq[tid] = q;
    __syncthreads();
    if (tid < 128) {
        s = ss[tid] + ss[tid + 128];
        q = sq[tid] + sq[tid + 128];
        atomicAdd(&g_sums[tid], s);
        atomicAdd(&g_sums[128 + tid], q);
    }
}

// BN normalize in place (and optionally also write a copy to `extra`)
__global__ void __launch_bounds__(256) k_norm(const float* __restrict__ gamma,
                                              const float* __restrict__ beta,
                                              float* __restrict__ extra, int also) {
    size_t idx = (size_t)blockIdx.x * 256 + threadIdx.x;
    size_t base = idx * 4;
    int c = (int)(base & 127);
    float4 s4 = *(const float4*)(g_sums + c);
    float4 q4 = *(const float4*)(g_sums + 128 + c);
    float4 g4 = *(const float4*)(gamma + c);
    float4 b4 = *(const float4*)(beta + c);
    const float inN = 1.f / 8192.f;
    float mu, var, a0, a1, a2, a3, t0, t1, t2, t3;
    mu = s4.x * inN; var = q4.x * inN - mu * mu; a0 = g4.x * rsqrtf(var + 1e-5f); t0 = b4.x - a0 * mu;
    mu = s4.y * inN; var = q4.y * inN - mu * mu; a1 = g4.y * rsqrtf(var + 1e-5f); t1 = b4.y - a1 * mu;
    mu = s4.z * inN; var = q4.z * inN - mu * mu; a2 = g4.z * rsqrtf(var + 1e-5f); t2 = b4.z - a2 * mu;
    mu = s4.w * inN; var = q4.w * inN - mu * mu; a3 = g4.w * rsqrtf(var + 1e-5f); t3 = b4.w - a3 * mu;
    float4 v = *(const float4*)(g_H + base);
    v.x = v.x * a0 + t0; v.y = v.y * a1 + t1; v.z = v.z * a2 + t2; v.w = v.w * a3 + t3;
    *(float4*)(g_H + base) = v;
    if (also) *(float4*)(extra + base) = v;
}

// ---------------- launch ----------------
extern "C" void kernel_launch(void* const* d_in, const int* in_sizes, int n_in,
                              void* d_out, int out_size) {
    const float* x     = (const float*)d_in[0];
    const float* adj   = (const float*)d_in[1];
    const float* mask  = (const float*)d_in[2];
    const float* noise = (const float*)d_in[3];
    const float* eW = (const float*)d_in[4];
    const float* eb = (const float*)d_in[5];
    const float* ea = (const float*)d_in[6];
    const float* eg = (const float*)d_in[7];
    const float* eB = (const float*)d_in[8];
    const float* dW = (const float*)d_in[9];
    const float* db = (const float*)d_in[10];
    const float* da = (const float*)d_in[11];
    const float* dg = (const float*)d_in[12];
    const float* dB = (const float*)d_in[13];
    float* out = (float*)d_out;

    const int SMEM_BIG = 3 * 24576;                   // 73728
    const int SMEM_HW  = (64 * 129 + 128 * 128) * 4;  // 98560
    cudaFuncSetAttribute(k_big, cudaFuncAttributeMaxDynamicSharedMemorySize, SMEM_BIG);
    cudaFuncSetAttribute(k_hw,  cudaFuncAttributeMaxDynamicSharedMemorySize, SMEM_HW);

    k_convert<<<32768, 256>>>(adj);
    k_mask<<<1024, 256>>>(x, mask, noise, out);

    // encoder: 5 x (GCN -> BN); BN of layer 5 also writes encoded (section 1)
    for (int i = 0; i < 5; i++) {
        k_hw<<<128, 256, SMEM_HW>>>(eW + (size_t)i * 16384);
        k_big<<<128, 256, SMEM_BIG>>>(eb + i * 128, ea + i, out, 0);
        k_colstats<<<64, 256>>>();
        k_norm<<<1024, 256>>>(eg + i * 128, eB + i * 128, out + (size_t)SEC, (i == 4) ? 1 : 0);
    }
    // decoder: 4 x (GCN -> BN), then final GCN straight to out section 2
    for (int i = 0; i < 4; i++) {
        k_hw<<<128, 256, SMEM_HW>>>(dW + (size_t)i * 16384);
        k_big<<<128, 256, SMEM_BIG>>>(db + i * 128, da + i, out, 0);
        k_colstats<<<64, 256>>>();
        k_norm<<<1024, 256>>>(dg + i * 128, dB + i * 128, out, 0);
    }
    k_hw<<<128, 256, SMEM_HW>>>(dW + (size_t)4 * 16384);
    k_big<<<128, 256, SMEM_BIG>>>(db + 4 * 128, da + 4, out + 2 * (size_t)SEC, 1);
}